// round 3
// baseline (speedup 1.0000x reference)
#include <cuda_runtime.h>

#define N_ATOMS 320
#define NWARPS_BLK 4
#define NTHREADS (NWARPS_BLK * 32)
#define NBLOCKS (N_ATOMS / NWARPS_BLK)
#define CAPN 128

// cos(sqrt(y)), degree-9 Taylor in y; |err| < 4e-9 for y in [0, pi^2]
__device__ __forceinline__ float cos_sqrt_poly(float y) {
    float p = -1.56192070e-16f;
    p = fmaf(p, y,  4.77947733e-14f);
    p = fmaf(p, y, -1.14707456e-11f);
    p = fmaf(p, y,  2.08767570e-9f);
    p = fmaf(p, y, -2.75573192e-7f);
    p = fmaf(p, y,  2.48015873e-5f);
    p = fmaf(p, y, -1.38888889e-3f);
    p = fmaf(p, y,  4.16666667e-2f);
    p = fmaf(p, y, -0.5f);
    p = fmaf(p, y,  1.0f);
    return p;
}

__global__ __launch_bounds__(NTHREADS, 1)
void featurizer_kernel(const float* __restrict__ atomic_numbers,
                       const float* __restrict__ coords,
                       float* __restrict__ out)
{
    __shared__ float sc[N_ATOMS * 3];
    __shared__ float sdx[NWARPS_BLK * CAPN], sdy[NWARPS_BLK * CAPN], sdz[NWARPS_BLK * CAPN];
    __shared__ float sr2[NWARPS_BLK * CAPN], sfc[NWARPS_BLK * CAPN];
    __shared__ float se1[NWARPS_BLK * CAPN], se5[NWARPS_BLK * CAPN], sir[NWARPS_BLK * CAPN];

    const int tid  = threadIdx.x;
    const int lane = tid & 31;
    const int warp = tid >> 5;
    const int i    = blockIdx.x * NWARPS_BLK + warp;   // this warp's atom
    const int wb   = warp * CAPN;

    // Stage all coordinates once per block
    for (int idx = tid; idx < N_ATOMS * 3; idx += NTHREADS) sc[idx] = coords[idx];
    __syncthreads();

    const float xi = sc[3 * i + 0], yi = sc[3 * i + 1], zi = sc[3 * i + 2];
    const float PI2_36 = 0.27415567780803773f;   // (pi/6)^2
    const unsigned lt = (1u << lane) - 1u;

    // ---- Phase 1: radial sums + compacted per-warp neighbor arrays ----
    float rad[13];
    #pragma unroll
    for (int q = 0; q < 13; q++) rad[q] = 0.f;

    int base = 0;
    #pragma unroll
    for (int j0 = 0; j0 < N_ATOMS; j0 += 32) {
        int j = j0 + lane;
        float dx = xi - sc[3 * j + 0];
        float dy = yi - sc[3 * j + 1];
        float dz = zi - sc[3 * j + 2];
        float r2 = dx * dx + dy * dy + dz * dz;
        bool pred = (j != i) && (r2 < 36.0f);
        unsigned m = __ballot_sync(0xffffffffu, pred);
        if (pred) {
            int pos = base + __popc(m & lt);
            float rs   = rsqrtf(r2);
            float r    = r2 * rs;
            float fc   = 0.5f * (cos_sqrt_poly(PI2_36 * r2) + 1.0f);
            float e05  = __expf(-0.5f * r2);
            float e1g2 = e05 * e05, e2g2 = e1g2 * e1g2, e4g2 = e2g2 * e2g2;
            float gsh  = __expf(fmaf(3.0f, r, -4.5f));       // exp(3r - 4.5)
            float f05  = e05 * gsh;                          // exp(-0.5 (r-3)^2)
            float f1 = f05 * f05, f2 = f1 * f1, f4 = f2 * f2;
            float c1 = __cosf(0.5f * r);                     // Chebyshev chain
            float c2 = fmaf(2.f * c1, c1, -1.f);
            float c3 = fmaf(2.f * c1, c2, -c1);
            float c4 = fmaf(2.f * c1, c3, -c2);
            rad[0] += fc;
            rad[1] += e05 * fc;  rad[2] += e1g2 * fc;  rad[3] += e2g2 * fc;  rad[4] += e4g2 * fc;
            rad[5] += f05 * fc;  rad[6] += f1 * fc;    rad[7] += f2 * fc;    rad[8] += f4 * fc;
            rad[9] += c1 * fc;   rad[10] += c2 * fc;   rad[11] += c3 * fc;   rad[12] += c4 * fc;
            sdx[wb + pos] = dx; sdy[wb + pos] = dy; sdz[wb + pos] = dz;
            sr2[wb + pos] = r2; sfc[wb + pos] = fc;
            se1[wb + pos] = __expf(-0.1f * r2);
            se5[wb + pos] = e05;
            sir[wb + pos] = rs;
        }
        base += __popc(m);
    }
    const int M = base;

    // warp-reduce 13 radial sums to lane 0
    #pragma unroll
    for (int q = 0; q < 13; q++) {
        float v = rad[q];
        #pragma unroll
        for (int off = 16; off > 0; off >>= 1) v += __shfl_down_sync(0xffffffffu, v, off);
        rad[q] = v;
    }
    if (lane == 0) {
        out[i * 22 + 0] = atomic_numbers[i];
        #pragma unroll
        for (int q = 0; q < 13; q++) out[i * 22 + 1 + q] = rad[q];
    }
    __syncwarp();   // neighbor arrays visible to whole warp

    // ---- Phase 2: angular sums over unordered pairs a>b ----
    float s[8];
    #pragma unroll
    for (int q = 0; q < 8; q++) s[q] = 0.f;

    const int npairs = (M * (M - 1)) >> 1;
    for (int p = lane; p < npairs; p += 32) {
        int a = (int)((1.0f + sqrtf(fmaf(8.0f, (float)p, 1.0f))) * 0.5f);
        while (((a * (a - 1)) >> 1) > p) a--;
        while ((((a + 1) * a) >> 1) <= p) a++;
        int b = p - ((a * (a - 1)) >> 1);
        int ja = wb + a, jb = wb + b;

        float dot = sdx[ja] * sdx[jb] + sdy[ja] * sdy[jb] + sdz[ja] * sdz[jb];
        float cosv = dot * sir[ja] * sir[jb];
        float R2p  = sr2[ja] + sr2[jb];
        float r2jk = fmaxf(fmaf(-2.0f, dot, R2p), 0.0f);

        float fcjk = (r2jk < 36.0f)
                   ? 0.5f * (cos_sqrt_poly(PI2_36 * r2jk) + 1.0f) : 0.0f;

        float ejk1 = __expf(-0.1f * r2jk);
        float t2 = ejk1 * ejk1, t4 = t2 * t2;
        float ejk5 = t4 * ejk1;                       // exp(-0.5 r2jk)

        float ep1 = se1[ja] * se1[jb];
        float ep5 = se5[ja] * se5[jb];
        float fc2 = sfc[ja] * sfc[jb];
        float fc3 = fc2 * fcjk;
        float et1 = ep1 * ejk1, et5 = ep5 * ejk5;

        float op = 1.0f + cosv, om = 1.0f - cosv;
        float a1 = om * om;          // (1-c)^2
        float op2 = op * op;
        float a2 = op2 * op2;        // (1+c)^4
        float a3 = a1 * a1;          // (1-c)^4

        float w41 = et1 * fc3, w45 = et5 * fc3;
        float w51 = ep1 * fc2, w55 = ep5 * fc2;
        s[0] += op * w41; s[1] += a1 * w41; s[2] += a2 * w45; s[3] += a3 * w45;
        s[4] += op * w51; s[5] += a1 * w51; s[6] += a2 * w55; s[7] += a3 * w55;
    }

    #pragma unroll
    for (int q = 0; q < 8; q++) {
        float v = s[q];
        #pragma unroll
        for (int off = 16; off > 0; off >>= 1) v += __shfl_down_sync(0xffffffffu, v, off);
        s[q] = v;
    }
    if (lane == 0) {
        const float scl[4] = {1.0f, 0.5f, 0.125f, 0.125f};  // 2^(1-zeta), unordered sum
        #pragma unroll
        for (int q = 0; q < 8; q++)
            out[i * 22 + 14 + q] = s[q] * scl[q & 3];
    }
}

extern "C" void kernel_launch(void* const* d_in, const int* in_sizes, int n_in,
                              void* d_out, int out_size)
{
    const float* atomic_numbers = (const float*)d_in[0]; // [320,1]
    const float* coordinates    = (const float*)d_in[1]; // [320,3]
    float* out = (float*)d_out;                          // [320,22]
    featurizer_kernel<<<NBLOCKS, NTHREADS>>>(atomic_numbers, coordinates, out);
}

// round 4
// speedup vs baseline: 1.5598x; 1.5598x over previous
#include <cuda_runtime.h>

#define N_ATOMS 320
#define NTHREADS 320
#define NWARPS 10
#define CAPN 96

// cos(sqrt(y)), degree-9 Taylor in y; |err| < 4e-9 for y in [0, pi^2]
__device__ __forceinline__ float cos_sqrt_poly(float y) {
    float p = -1.56192070e-16f;
    p = fmaf(p, y,  4.77947733e-14f);
    p = fmaf(p, y, -1.14707456e-11f);
    p = fmaf(p, y,  2.08767570e-9f);
    p = fmaf(p, y, -2.75573192e-7f);
    p = fmaf(p, y,  2.48015873e-5f);
    p = fmaf(p, y, -1.38888889e-3f);
    p = fmaf(p, y,  4.16666667e-2f);
    p = fmaf(p, y, -0.5f);
    p = fmaf(p, y,  1.0f);
    return p;
}

__global__ __launch_bounds__(NTHREADS, 2)
void featurizer_kernel(const float* __restrict__ atomic_numbers,
                       const float* __restrict__ coords,
                       float* __restrict__ out)
{
    // compact neighbor arrays (registers -> smem after prefix)
    __shared__ float sdx[CAPN], sdy[CAPN], sdz[CAPN];
    __shared__ float sr2[CAPN], sfc[CAPN], se1[CAPN], se5[CAPN], sir[CAPN];
    __shared__ int   swcnt[NWARPS];
    __shared__ float sRedA[NWARPS * 13];
    __shared__ float sRedB[NWARPS * 8];

    const int i    = blockIdx.x;
    const int tid  = threadIdx.x;       // == j, one thread per atom j
    const int lane = tid & 31;
    const int warp = tid >> 5;

    const float xi = __ldg(&coords[3 * i + 0]);
    const float yi = __ldg(&coords[3 * i + 1]);
    const float zi = __ldg(&coords[3 * i + 2]);
    const float PI2_36 = 0.27415567780803773f;   // (pi/6)^2

    // ---- Phase 1: one j per thread, all in registers ----
    const float dx = xi - __ldg(&coords[3 * tid + 0]);
    const float dy = yi - __ldg(&coords[3 * tid + 1]);
    const float dz = zi - __ldg(&coords[3 * tid + 2]);
    const float r2 = dx * dx + dy * dy + dz * dz;
    const bool pred = (tid != i) && (r2 < 36.0f);
    const unsigned m = __ballot_sync(0xffffffffu, pred);
    if (lane == 0) swcnt[warp] = __popc(m);

    float rad[13];
    #pragma unroll
    for (int q = 0; q < 13; q++) rad[q] = 0.f;

    float fc = 0.f, e05 = 0.f, e01 = 0.f, rs = 0.f;
    if (pred) {
        rs = rsqrtf(r2);
        float r = r2 * rs;
        fc  = 0.5f * (cos_sqrt_poly(PI2_36 * r2) + 1.0f);
        e05 = __expf(-0.5f * r2);
        e01 = __expf(-0.1f * r2);
        float e1g2 = e05 * e05, e2g2 = e1g2 * e1g2, e4g2 = e2g2 * e2g2;
        float gsh  = __expf(fmaf(3.0f, r, -4.5f));       // exp(3r - 4.5)
        float f05  = e05 * gsh;                          // exp(-0.5 (r-3)^2)
        float f1 = f05 * f05, f2 = f1 * f1, f4 = f2 * f2;
        float c1 = __cosf(0.5f * r);                     // Chebyshev chain
        float c2 = fmaf(2.f * c1, c1, -1.f);
        float c3 = fmaf(2.f * c1, c2, -c1);
        float c4 = fmaf(2.f * c1, c3, -c2);
        rad[0] = fc;
        rad[1] = e05 * fc;  rad[2] = e1g2 * fc;  rad[3] = e2g2 * fc;  rad[4] = e4g2 * fc;
        rad[5] = f05 * fc;  rad[6] = f1 * fc;    rad[7] = f2 * fc;    rad[8] = f4 * fc;
        rad[9] = c1 * fc;   rad[10] = c2 * fc;   rad[11] = c3 * fc;   rad[12] = c4 * fc;
    }
    __syncthreads();   // swcnt visible

    // ---- Compaction: prefix over warp counts, write registers to slot ----
    int M = 0;
    {
        int pfx = 0;
        #pragma unroll
        for (int w = 0; w < NWARPS; w++) {
            int c = swcnt[w];
            if (w < warp) pfx += c;
            M += c;
        }
        if (pred) {
            int pos = pfx + __popc(m & ((1u << lane) - 1u));
            if (pos < CAPN) {
                sdx[pos] = dx; sdy[pos] = dy; sdz[pos] = dz;
                sr2[pos] = r2; sfc[pos] = fc;
                se1[pos] = e01; se5[pos] = e05; sir[pos] = rs;
            }
        }
    }

    // ---- Radial warp-reduce (hides barrier skew), partials to smem ----
    #pragma unroll
    for (int q = 0; q < 13; q++) {
        float v = rad[q];
        #pragma unroll
        for (int off = 16; off > 0; off >>= 1) v += __shfl_down_sync(0xffffffffu, v, off);
        if (lane == 0) sRedA[warp * 13 + q] = v;
    }
    __syncthreads();   // compact arrays + sRedA visible

    // ---- Phase 2: angular sums over unordered pairs a>b (~2 iters) ----
    float s[8];
    #pragma unroll
    for (int q = 0; q < 8; q++) s[q] = 0.f;

    const int npairs = (M * (M - 1)) >> 1;
    for (int p = tid; p < npairs; p += NTHREADS) {
        int a = (int)((1.0f + sqrtf(fmaf(8.0f, (float)p, 1.0f))) * 0.5f);
        while (((a * (a - 1)) >> 1) > p) a--;
        while ((((a + 1) * a) >> 1) <= p) a++;
        int b = p - ((a * (a - 1)) >> 1);

        float dot = sdx[a] * sdx[b] + sdy[a] * sdy[b] + sdz[a] * sdz[b];
        float cosv = dot * sir[a] * sir[b];
        float R2p  = sr2[a] + sr2[b];
        float r2jk = fmaxf(fmaf(-2.0f, dot, R2p), 0.0f);

        float fcjk = (r2jk < 36.0f)
                   ? 0.5f * (cos_sqrt_poly(PI2_36 * r2jk) + 1.0f) : 0.0f;

        float ejk1 = __expf(-0.1f * r2jk);
        float t2 = ejk1 * ejk1, t4 = t2 * t2;
        float ejk5 = t4 * ejk1;                       // exp(-0.5 r2jk)

        float ep1 = se1[a] * se1[b];
        float ep5 = se5[a] * se5[b];
        float fc2 = sfc[a] * sfc[b];
        float fc3 = fc2 * fcjk;
        float et1 = ep1 * ejk1, et5 = ep5 * ejk5;

        float op = 1.0f + cosv, om = 1.0f - cosv;
        float a1 = om * om;          // (1-c)^2
        float op2 = op * op;
        float a2 = op2 * op2;        // (1+c)^4
        float a3 = a1 * a1;          // (1-c)^4

        float w41 = et1 * fc3, w45 = et5 * fc3;
        float w51 = ep1 * fc2, w55 = ep5 * fc2;
        s[0] += op * w41; s[1] += a1 * w41; s[2] += a2 * w45; s[3] += a3 * w45;
        s[4] += op * w51; s[5] += a1 * w51; s[6] += a2 * w55; s[7] += a3 * w55;
    }

    #pragma unroll
    for (int q = 0; q < 8; q++) {
        float v = s[q];
        #pragma unroll
        for (int off = 16; off > 0; off >>= 1) v += __shfl_down_sync(0xffffffffu, v, off);
        if (lane == 0) sRedB[warp * 8 + q] = v;
    }
    __syncthreads();

    // ---- Output: 22 columns ----
    if (tid == 0) out[i * 22 + 0] = __ldg(&atomic_numbers[i]);
    if (tid >= 1 && tid < 14) {
        int q = tid - 1;
        float v = 0.f;
        #pragma unroll
        for (int w = 0; w < NWARPS; w++) v += sRedA[w * 13 + q];
        out[i * 22 + tid] = v;
    }
    if (tid >= 14 && tid < 22) {
        int q = tid - 14;
        const float scl[4] = {1.0f, 0.5f, 0.125f, 0.125f};  // 2^(1-zeta), unordered sum
        float v = 0.f;
        #pragma unroll
        for (int w = 0; w < NWARPS; w++) v += sRedB[w * 8 + q];
        out[i * 22 + tid] = v * scl[q & 3];
    }
}

extern "C" void kernel_launch(void* const* d_in, const int* in_sizes, int n_in,
                              void* d_out, int out_size)
{
    const float* atomic_numbers = (const float*)d_in[0]; // [320,1]
    const float* coordinates    = (const float*)d_in[1]; // [320,3]
    float* out = (float*)d_out;                          // [320,22]
    featurizer_kernel<<<N_ATOMS, NTHREADS>>>(atomic_numbers, coordinates, out);
}

// round 5
// speedup vs baseline: 1.9107x; 1.2250x over previous
#include <cuda_runtime.h>

#define N_ATOMS 320
#define NTHREADS 320
#define NWARPS 10
#define CAPN 96

// cos(sqrt(y)), degree-9 Taylor in y; |err| < 4e-9 for y in [0, pi^2]
__device__ __forceinline__ float cos_sqrt_poly(float y) {
    float p = -1.56192070e-16f;
    p = fmaf(p, y,  4.77947733e-14f);
    p = fmaf(p, y, -1.14707456e-11f);
    p = fmaf(p, y,  2.08767570e-9f);
    p = fmaf(p, y, -2.75573192e-7f);
    p = fmaf(p, y,  2.48015873e-5f);
    p = fmaf(p, y, -1.38888889e-3f);
    p = fmaf(p, y,  4.16666667e-2f);
    p = fmaf(p, y, -0.5f);
    p = fmaf(p, y,  1.0f);
    return p;
}

__global__ __launch_bounds__(NTHREADS, 2)
void featurizer_kernel(const float* __restrict__ atomic_numbers,
                       const float* __restrict__ coords,
                       float* __restrict__ out)
{
    __shared__ float4 nA[CAPN];              // {dx, dy, dz, r2}
    __shared__ float4 nB[CAPN];              // {fc, e01, e05, rs}
    __shared__ float  sRadT[13][NTHREADS];   // transposed radial terms
    __shared__ float  sAng[8][NTHREADS];     // transposed angular partials
    __shared__ int    swcnt[NWARPS];

    const int i    = blockIdx.x;
    const int tid  = threadIdx.x;            // one thread per atom j
    const int lane = tid & 31;
    const int warp = tid >> 5;

    const float xi = __ldg(&coords[3 * i + 0]);
    const float yi = __ldg(&coords[3 * i + 1]);
    const float zi = __ldg(&coords[3 * i + 2]);
    const float PI2_36 = 0.27415567780803773f;   // (pi/6)^2

    // ---- Phase 1: one j per thread, all in registers ----
    const float dx = xi - __ldg(&coords[3 * tid + 0]);
    const float dy = yi - __ldg(&coords[3 * tid + 1]);
    const float dz = zi - __ldg(&coords[3 * tid + 2]);
    const float r2 = dx * dx + dy * dy + dz * dz;
    const bool pred = (tid != i) && (r2 < 36.0f);
    const unsigned m = __ballot_sync(0xffffffffu, pred);
    if (lane == 0) swcnt[warp] = __popc(m);

    float radv[13];
    #pragma unroll
    for (int q = 0; q < 13; q++) radv[q] = 0.f;

    float fc = 0.f, e05 = 0.f, e01 = 0.f, rs = 0.f;
    if (pred) {
        rs  = rsqrtf(r2);
        float r = r2 * rs;
        fc  = 0.5f * (cos_sqrt_poly(PI2_36 * r2) + 1.0f);
        e05 = __expf(-0.5f * r2);
        e01 = __expf(-0.1f * r2);
        float e1g2 = e05 * e05, e2g2 = e1g2 * e1g2, e4g2 = e2g2 * e2g2;
        float gsh  = __expf(fmaf(3.0f, r, -4.5f));       // exp(3r - 4.5)
        float f05  = e05 * gsh;                          // exp(-0.5 (r-3)^2)
        float f1 = f05 * f05, f2 = f1 * f1, f4 = f2 * f2;
        float c1 = __cosf(0.5f * r);                     // Chebyshev chain
        float c2 = fmaf(2.f * c1, c1, -1.f);
        float c3 = fmaf(2.f * c1, c2, -c1);
        float c4 = fmaf(2.f * c1, c3, -c2);
        radv[0] = fc;
        radv[1] = e05 * fc;  radv[2] = e1g2 * fc;  radv[3] = e2g2 * fc;  radv[4] = e4g2 * fc;
        radv[5] = f05 * fc;  radv[6] = f1 * fc;    radv[7] = f2 * fc;    radv[8] = f4 * fc;
        radv[9] = c1 * fc;   radv[10] = c2 * fc;   radv[11] = c3 * fc;   radv[12] = c4 * fc;
    }
    #pragma unroll
    for (int q = 0; q < 13; q++) sRadT[q][tid] = radv[q];

    __syncthreads();   // sRadT + swcnt visible

    // ---- Compaction: prefix over warp counts, vectorized stores ----
    int M = 0;
    {
        int pfx = 0;
        #pragma unroll
        for (int w = 0; w < NWARPS; w++) {
            int c = swcnt[w];
            if (w < warp) pfx += c;
            M += c;
        }
        if (pred) {
            int pos = pfx + __popc(m & ((1u << lane) - 1u));
            if (pos < CAPN) {
                nA[pos] = make_float4(dx, dy, dz, r2);
                nB[pos] = make_float4(fc, e01, e05, rs);
            }
        }
    }

    // ---- Radial channel sums (overlaps compaction, reads pre-barrier sRadT) ----
    for (int ch = warp; ch < 13; ch += NWARPS) {
        float v = 0.f;
        #pragma unroll
        for (int t = 0; t < NTHREADS / 32; t++) v += sRadT[ch][lane + 32 * t];
        #pragma unroll
        for (int off = 16; off > 0; off >>= 1) v += __shfl_down_sync(0xffffffffu, v, off);
        if (lane == 0) out[i * 22 + 1 + ch] = v;
    }
    __syncthreads();   // nA / nB visible

    // ---- Phase 2: angular sums over unordered pairs a>b ----
    float s[8];
    #pragma unroll
    for (int q = 0; q < 8; q++) s[q] = 0.f;

    const int Mc = (M < CAPN) ? M : CAPN;
    const int npairs = (Mc * (Mc - 1)) >> 1;
    for (int p = tid; p < npairs; p += NTHREADS) {
        int a = (int)((1.0f + sqrtf(fmaf(8.0f, (float)p, 1.0f))) * 0.5f);
        while (((a * (a - 1)) >> 1) > p) a--;
        while ((((a + 1) * a) >> 1) <= p) a++;
        int b = p - ((a * (a - 1)) >> 1);

        float4 va = nA[a], vb = nA[b];
        float4 wa = nB[a], wb = nB[b];

        float dot = va.x * vb.x + va.y * vb.y + va.z * vb.z;
        float cosv = dot * wa.w * wb.w;
        float R2p  = va.w + vb.w;
        float r2jk = fmaxf(fmaf(-2.0f, dot, R2p), 0.0f);

        float fcjk = (r2jk < 36.0f)
                   ? 0.5f * (cos_sqrt_poly(PI2_36 * r2jk) + 1.0f) : 0.0f;

        float ejk1 = __expf(-0.1f * r2jk);
        float t2 = ejk1 * ejk1, t4 = t2 * t2;
        float ejk5 = t4 * ejk1;                       // exp(-0.5 r2jk)

        float ep1 = wa.y * wb.y;
        float ep5 = wa.z * wb.z;
        float fc2 = wa.x * wb.x;
        float fc3 = fc2 * fcjk;
        float et1 = ep1 * ejk1, et5 = ep5 * ejk5;

        float op = 1.0f + cosv, om = 1.0f - cosv;
        float a1 = om * om;          // (1-c)^2
        float op2 = op * op;
        float a2 = op2 * op2;        // (1+c)^4
        float a3 = a1 * a1;          // (1-c)^4

        float w41 = et1 * fc3, w45 = et5 * fc3;
        float w51 = ep1 * fc2, w55 = ep5 * fc2;
        s[0] += op * w41; s[1] += a1 * w41; s[2] += a2 * w45; s[3] += a3 * w45;
        s[4] += op * w51; s[5] += a1 * w51; s[6] += a2 * w55; s[7] += a3 * w55;
    }

    #pragma unroll
    for (int q = 0; q < 8; q++) sAng[q][tid] = s[q];
    __syncthreads();

    // ---- Angular channel sums: one channel per warp (warps 0-7) ----
    if (warp < 8) {
        const float scl[8] = {1.0f, 0.5f, 0.125f, 0.125f,
                              1.0f, 0.5f, 0.125f, 0.125f};
        float v = 0.f;
        #pragma unroll
        for (int t = 0; t < NTHREADS / 32; t++) v += sAng[warp][lane + 32 * t];
        #pragma unroll
        for (int off = 16; off > 0; off >>= 1) v += __shfl_down_sync(0xffffffffu, v, off);
        if (lane == 0) out[i * 22 + 14 + warp] = v * scl[warp];
    }
    if (tid == NTHREADS - 1) out[i * 22 + 0] = __ldg(&atomic_numbers[i]);
}

extern "C" void kernel_launch(void* const* d_in, const int* in_sizes, int n_in,
                              void* d_out, int out_size)
{
    const float* atomic_numbers = (const float*)d_in[0]; // [320,1]
    const float* coordinates    = (const float*)d_in[1]; // [320,3]
    float* out = (float*)d_out;                          // [320,22]
    featurizer_kernel<<<N_ATOMS, NTHREADS>>>(atomic_numbers, coordinates, out);
}

// round 6
// speedup vs baseline: 1.9742x; 1.0332x over previous
#include <cuda_runtime.h>

#define N_ATOMS 320
#define NTHREADS 320
#define NWARPS 10
#define CAPN 96

// cos(sqrt(y)), degree-9 Taylor in y; |err| < 4e-9 for y in [0, pi^2]
__device__ __forceinline__ float cos_sqrt_poly(float y) {
    float p = -1.56192070e-16f;
    p = fmaf(p, y,  4.77947733e-14f);
    p = fmaf(p, y, -1.14707456e-11f);
    p = fmaf(p, y,  2.08767570e-9f);
    p = fmaf(p, y, -2.75573192e-7f);
    p = fmaf(p, y,  2.48015873e-5f);
    p = fmaf(p, y, -1.38888889e-3f);
    p = fmaf(p, y,  4.16666667e-2f);
    p = fmaf(p, y, -0.5f);
    p = fmaf(p, y,  1.0f);
    return p;
}

__global__ __launch_bounds__(NTHREADS, 4)
void featurizer_kernel(const float* __restrict__ atomic_numbers,
                       const float* __restrict__ coords,
                       float* __restrict__ out)
{
    __shared__ float4 nA[CAPN];              // {dx, dy, dz, r2}
    __shared__ float4 nB[CAPN];              // {fc, e01, e05, rs}
    __shared__ union {
        float radT[13][NTHREADS];            // transposed radial terms (live: barrier1..barrier2)
        float ang[8][NTHREADS];              // transposed angular partials (live: after barrier2)
    } red;
    __shared__ int    swcnt[NWARPS];

    const int i    = blockIdx.x;
    const int tid  = threadIdx.x;            // one thread per atom j
    const int lane = tid & 31;
    const int warp = tid >> 5;

    const float xi = __ldg(&coords[3 * i + 0]);
    const float yi = __ldg(&coords[3 * i + 1]);
    const float zi = __ldg(&coords[3 * i + 2]);
    const float PI2_36 = 0.27415567780803773f;   // (pi/6)^2

    // ---- Phase 1: one j per thread, all in registers ----
    const float dx = xi - __ldg(&coords[3 * tid + 0]);
    const float dy = yi - __ldg(&coords[3 * tid + 1]);
    const float dz = zi - __ldg(&coords[3 * tid + 2]);
    const float r2 = dx * dx + dy * dy + dz * dz;
    const bool pred = (tid != i) && (r2 < 36.0f);
    const unsigned m = __ballot_sync(0xffffffffu, pred);
    if (lane == 0) swcnt[warp] = __popc(m);

    float radv[13];
    #pragma unroll
    for (int q = 0; q < 13; q++) radv[q] = 0.f;

    float fc = 0.f, e05 = 0.f, e01 = 0.f, rs = 0.f;
    if (pred) {
        rs  = rsqrtf(r2);
        float r = r2 * rs;
        fc  = 0.5f * (cos_sqrt_poly(PI2_36 * r2) + 1.0f);
        e05 = __expf(-0.5f * r2);
        e01 = __expf(-0.1f * r2);
        float e1g2 = e05 * e05, e2g2 = e1g2 * e1g2, e4g2 = e2g2 * e2g2;
        float gsh  = __expf(fmaf(3.0f, r, -4.5f));       // exp(3r - 4.5)
        float f05  = e05 * gsh;                          // exp(-0.5 (r-3)^2)
        float f1 = f05 * f05, f2 = f1 * f1, f4 = f2 * f2;
        float c1 = __cosf(0.5f * r);                     // Chebyshev chain
        float c2 = fmaf(2.f * c1, c1, -1.f);
        float c3 = fmaf(2.f * c1, c2, -c1);
        float c4 = fmaf(2.f * c1, c3, -c2);
        radv[0] = fc;
        radv[1] = e05 * fc;  radv[2] = e1g2 * fc;  radv[3] = e2g2 * fc;  radv[4] = e4g2 * fc;
        radv[5] = f05 * fc;  radv[6] = f1 * fc;    radv[7] = f2 * fc;    radv[8] = f4 * fc;
        radv[9] = c1 * fc;   radv[10] = c2 * fc;   radv[11] = c3 * fc;   radv[12] = c4 * fc;
    }
    #pragma unroll
    for (int q = 0; q < 13; q++) red.radT[q][tid] = radv[q];

    __syncthreads();   // red.radT + swcnt visible

    // ---- Compaction: prefix over warp counts, vectorized stores ----
    int M = 0;
    {
        int pfx = 0;
        #pragma unroll
        for (int w = 0; w < NWARPS; w++) {
            int c = swcnt[w];
            if (w < warp) pfx += c;
            M += c;
        }
        if (pred) {
            int pos = pfx + __popc(m & ((1u << lane) - 1u));
            if (pos < CAPN) {
                nA[pos] = make_float4(dx, dy, dz, r2);
                nB[pos] = make_float4(fc, e01, e05, rs);
            }
        }
    }

    // ---- Radial channel sums (overlaps compaction, reads pre-barrier radT) ----
    for (int ch = warp; ch < 13; ch += NWARPS) {
        float v = 0.f;
        #pragma unroll
        for (int t = 0; t < NTHREADS / 32; t++) v += red.radT[ch][lane + 32 * t];
        #pragma unroll
        for (int off = 16; off > 0; off >>= 1) v += __shfl_down_sync(0xffffffffu, v, off);
        if (lane == 0) out[i * 22 + 1 + ch] = v;
    }
    __syncthreads();   // nA / nB visible; radT dead -> ang may be written

    // ---- Phase 2: angular sums over unordered pairs a>b ----
    float s[8];
    #pragma unroll
    for (int q = 0; q < 8; q++) s[q] = 0.f;

    const int Mc = (M < CAPN) ? M : CAPN;
    const int npairs = (Mc * (Mc - 1)) >> 1;
    for (int p = tid; p < npairs; p += NTHREADS) {
        int a = (int)((1.0f + sqrtf(fmaf(8.0f, (float)p, 1.0f))) * 0.5f);
        while (__builtin_expect(((a * (a - 1)) >> 1) > p, 0)) a--;
        while (__builtin_expect((((a + 1) * a) >> 1) <= p, 0)) a++;
        int b = p - ((a * (a - 1)) >> 1);

        float4 va = nA[a], vb = nA[b];
        float4 wa = nB[a], wb = nB[b];

        float dot = va.x * vb.x + va.y * vb.y + va.z * vb.z;
        float cosv = dot * wa.w * wb.w;
        float R2p  = va.w + vb.w;
        float r2jk = fmaxf(fmaf(-2.0f, dot, R2p), 0.0f);

        float fcjk = (r2jk < 36.0f)
                   ? 0.5f * (cos_sqrt_poly(PI2_36 * r2jk) + 1.0f) : 0.0f;

        float ejk1 = __expf(-0.1f * r2jk);
        float t2 = ejk1 * ejk1, t4 = t2 * t2;
        float ejk5 = t4 * ejk1;                       // exp(-0.5 r2jk)

        float ep1 = wa.y * wb.y;
        float ep5 = wa.z * wb.z;
        float fc2 = wa.x * wb.x;
        float fc3 = fc2 * fcjk;
        float et1 = ep1 * ejk1, et5 = ep5 * ejk5;

        float op = 1.0f + cosv, om = 1.0f - cosv;
        float a1 = om * om;          // (1-c)^2
        float op2 = op * op;
        float a2 = op2 * op2;        // (1+c)^4
        float a3 = a1 * a1;          // (1-c)^4

        float w41 = et1 * fc3, w45 = et5 * fc3;
        float w51 = ep1 * fc2, w55 = ep5 * fc2;
        s[0] += op * w41; s[1] += a1 * w41; s[2] += a2 * w45; s[3] += a3 * w45;
        s[4] += op * w51; s[5] += a1 * w51; s[6] += a2 * w55; s[7] += a3 * w55;
    }

    #pragma unroll
    for (int q = 0; q < 8; q++) red.ang[q][tid] = s[q];
    __syncthreads();

    // ---- Angular channel sums: one channel per warp (warps 0-7) ----
    if (warp < 8) {
        const float scl[8] = {1.0f, 0.5f, 0.125f, 0.125f,
                              1.0f, 0.5f, 0.125f, 0.125f};
        float v = 0.f;
        #pragma unroll
        for (int t = 0; t < NTHREADS / 32; t++) v += red.ang[warp][lane + 32 * t];
        #pragma unroll
        for (int off = 16; off > 0; off >>= 1) v += __shfl_down_sync(0xffffffffu, v, off);
        if (lane == 0) out[i * 22 + 14 + warp] = v * scl[warp];
    }
    if (tid == NTHREADS - 1) out[i * 22 + 0] = __ldg(&atomic_numbers[i]);
}

extern "C" void kernel_launch(void* const* d_in, const int* in_sizes, int n_in,
                              void* d_out, int out_size)
{
    const float* atomic_numbers = (const float*)d_in[0]; // [320,1]
    const float* coordinates    = (const float*)d_in[1]; // [320,3]
    float* out = (float*)d_out;                          // [320,22]
    featurizer_kernel<<<N_ATOMS, NTHREADS>>>(atomic_numbers, coordinates, out);
}